// round 1
// baseline (speedup 1.0000x reference)
#include <cuda_runtime.h>

// Problem constants (fixed by the dataset)
#define NATOMS 6144
#define FDIM   128
#define HDIM   64      // F/2
#define NMOL   48
#define ABLK   16      // atoms per block in the atom kernel
#define NATOM_BLOCKS (NATOMS / ABLK)   // 384

// Scratch (device globals — no allocations allowed)
__device__ float  g_q[NATOMS];       // raw charge (pre-neutralization)
__device__ float  g_sc6[NATOMS];     // sqrt(c6)
__device__ float  g_mu[NATOMS * 3];  // dipole vectors
__device__ double g_qsum[NMOL];      // per-molecule charge sum
__device__ int    g_cnt[NMOL];       // per-molecule atom count
__device__ int    g_segend[NMOL];    // exclusive end index of each molecule (batch is sorted)
__device__ double g_energy;          // global energy accumulator

// ---------------------------------------------------------------------------
// Kernel 0: zero the per-call scratch (graph replays must be idempotent)
// ---------------------------------------------------------------------------
__global__ void init_kernel() {
    int t = threadIdx.x;
    if (t < NMOL) { g_qsum[t] = 0.0; g_cnt[t] = 0; g_segend[t] = 0; }
    if (t == 0) g_energy = 0.0;
}

// ---------------------------------------------------------------------------
// Kernel 1: per-atom MLPs (charge q, sqrt(c6), dipole mu) + segment metadata
//   Block = 128 threads, handles ABLK=16 atoms.
//   Weights (128x64) staged in shared memory; h0 rows staged in shared memory.
//   Thread layout for the hidden layer: t = tid&63 owns hidden unit t,
//   half = tid>>6 owns 8 of the 16 atoms; each thread carries hid[8] in regs.
// ---------------------------------------------------------------------------
__global__ __launch_bounds__(128) void atom_kernel(
    const float* __restrict__ h0, const float* __restrict__ h1,
    const int*   __restrict__ batch,
    const float* __restrict__ qW1, const float* __restrict__ qb1,
    const float* __restrict__ qW2, const float* __restrict__ qb2,
    const float* __restrict__ cW1, const float* __restrict__ cb1,
    const float* __restrict__ cW2, const float* __restrict__ cb2,
    const float* __restrict__ muW)
{
    __shared__ float sH0[ABLK][FDIM];        // 8 KB
    __shared__ float sW[FDIM * HDIM];        // 32 KB (qW1, then cW1, then muW reuse)
    __shared__ float sPart[4][ABLK / 2];     // warp partial sums

    const int tid  = threadIdx.x;
    const int base = blockIdx.x * ABLK;
    const int t    = tid & 63;
    const int half = tid >> 6;
    const int w    = tid >> 5;
    const int lane = tid & 31;

    // Stage the 16 h0 rows (coalesced)
    for (int idx = tid; idx < ABLK * FDIM; idx += 128) {
        int a = idx >> 7, f = idx & 127;
        sH0[a][f] = h0[(size_t)(base + a) * FDIM + f];
    }

    for (int phase = 0; phase < 2; phase++) {
        const float* W1 = phase ? cW1 : qW1;
        const float* b1 = phase ? cb1 : qb1;
        const float* W2 = phase ? cW2 : qW2;
        const float* b2 = phase ? cb2 : qb2;

        __syncthreads();   // previous users of sW / sPart done
        for (int idx = tid; idx < FDIM * HDIM; idx += 128) sW[idx] = W1[idx];
        __syncthreads();

        float hid[8];
        #pragma unroll
        for (int a = 0; a < 8; a++) hid[a] = 0.0f;

        #pragma unroll 4
        for (int f4 = 0; f4 < FDIM / 4; f4++) {
            const float w0 = sW[(4 * f4 + 0) * HDIM + t];
            const float w1 = sW[(4 * f4 + 1) * HDIM + t];
            const float w2 = sW[(4 * f4 + 2) * HDIM + t];
            const float w3 = sW[(4 * f4 + 3) * HDIM + t];
            #pragma unroll
            for (int a = 0; a < 8; a++) {
                const float4 h = *reinterpret_cast<const float4*>(&sH0[half * 8 + a][4 * f4]);
                hid[a] = fmaf(h.x, w0, hid[a]);
                hid[a] = fmaf(h.y, w1, hid[a]);
                hid[a] = fmaf(h.z, w2, hid[a]);
                hid[a] = fmaf(h.w, w3, hid[a]);
            }
        }

        const float bias1 = b1[t];
        const float w2c   = W2[t];
        float v[8];
        #pragma unroll
        for (int a = 0; a < 8; a++) {
            float x = hid[a] + bias1;
            float s = 1.0f / (1.0f + expf(-x));   // sigmoid (full precision; tiny count)
            v[a] = x * s * w2c;                    // silu * W2
        }
        // warp-level reduce each of the 8 per-atom partials
        #pragma unroll
        for (int a = 0; a < 8; a++) {
            #pragma unroll
            for (int o = 16; o > 0; o >>= 1)
                v[a] += __shfl_down_sync(0xffffffffu, v[a], o);
        }
        if (lane == 0) {
            #pragma unroll
            for (int a = 0; a < 8; a++) sPart[w][a] = v[a];
        }
        __syncthreads();
        if (tid < ABLK) {
            const int a = tid;
            const int hsel = a >> 3;
            const float val = sPart[2 * hsel][a & 7] + sPart[2 * hsel + 1][a & 7] + b2[0];
            const int i = base + a;
            if (phase == 0) {
                g_q[i] = val;
                atomicAdd(&g_qsum[batch[i]], (double)val);
            } else {
                // softplus (numerically stable), then sqrt for c6_ij = sqrt(ci)*sqrt(cj)
                const float sp = fmaxf(val, 0.0f) + log1pf(expf(-fabsf(val)));
                g_sc6[i] = sqrtf(sp);
            }
        }
    }

    // mu = h1 @ muW  : reuse sW[0..127] for muW
    __syncthreads();
    if (tid < FDIM) sW[tid] = muW[tid];
    __syncthreads();
    for (int a = 4 * w; a < 4 * w + 4; a++) {
        const int i = base + a;
        const float* hrow = h1 + (size_t)i * 3 * FDIM;
        #pragma unroll
        for (int d = 0; d < 3; d++) {
            float p = 0.0f;
            for (int f = lane; f < FDIM; f += 32)
                p = fmaf(hrow[d * FDIM + f], sW[f], p);
            #pragma unroll
            for (int o = 16; o > 0; o >>= 1)
                p += __shfl_down_sync(0xffffffffu, p, o);
            if (lane == 0) g_mu[3 * i + d] = p;
        }
    }

    // per-molecule count + segment end (batch is sorted)
    if (tid < ABLK) {
        const int i = base + tid;
        const int b = batch[i];
        atomicAdd(&g_cnt[b], 1);
        if (i == NATOMS - 1 || batch[i + 1] != b) g_segend[b] = i + 1;
    }
}

// ---------------------------------------------------------------------------
// Kernel 2: pairwise energy. One warp per atom i; lanes stride over j in
// (i, segend) — i<j only (all three energy terms are symmetric, so the
// reference's 0.5 * sum over ordered pairs equals one pass over unordered
// pairs). MUFU budget per pair: 1 rsqrt + 1 ex2 + 1 rcp (the two denominators
// share a single reciprocal via 1/(a*b)).
// ---------------------------------------------------------------------------
__global__ __launch_bounds__(256) void pair_kernel(
    const float* __restrict__ pos, const int* __restrict__ batch)
{
    const int gw   = (blockIdx.x * blockDim.x + threadIdx.x) >> 5;
    const int lane = threadIdx.x & 31;
    __shared__ double sAcc;
    if (threadIdx.x == 0) sAcc = 0.0;
    __syncthreads();

    double acc = 0.0;
    if (gw < NATOMS) {
        const int i = gw;
        const int b = batch[i];
        const int e = g_segend[b];
        const float qm  = (float)(g_qsum[b] / (double)max(g_cnt[b], 1));
        const float qi  = g_q[i] - qm;
        const float pix = pos[3 * i], piy = pos[3 * i + 1], piz = pos[3 * i + 2];
        const float si  = g_sc6[i];
        const float mix = g_mu[3 * i], miy = g_mu[3 * i + 1], miz = g_mu[3 * i + 2];

        for (int j = i + 1 + lane; j < e; j += 32) {
            const float dx = pix - pos[3 * j];
            const float dy = piy - pos[3 * j + 1];
            const float dz = piz - pos[3 * j + 2];
            const float d2r  = dx * dx + dy * dy + dz * dz;   // raw dist_sq
            const float d2   = d2r + 1e-8f;
            const float invd = rsqrtf(d2);                    // 1/dist  (MUFU 1)
            const float dist = d2 * invd;                     // sqrt(d2)

            // Coulomb: q_i q_j / d * (1 - exp(-d/2)) * 14.399
            const float qj    = g_q[j] - qm;
            const float taper = 1.0f - __expf(-0.5f * dist);  // MUFU 2
            const float ec    = qi * qj * invd * taper * 14.399f;

            // shared reciprocal for vdW and dipole denominators   (MUFU 3)
            const float r6    = d2r * d2r * d2r;
            const float aden  = r6 + 20.0f;
            const float bden  = d2r * dist + 10.0f;
            const float invab = __fdividef(1.0f, aden * bden);

            // vdW: -sqrt(c6_i c6_j) / (r^6 + 20)
            const float ev = -si * g_sc6[j] * (invab * bden);

            // dipole-dipole
            const float mjx = g_mu[3 * j], mjy = g_mu[3 * j + 1], mjz = g_mu[3 * j + 2];
            const float mumu = mix * mjx + miy * mjy + miz * mjz;
            const float di   = (mix * dx + miy * dy + miz * dz) * invd;
            const float dj   = (mjx * dx + mjy * dy + mjz * dz) * invd;
            const float ed   = (mumu - 3.0f * di * dj) * (invab * aden);

            acc += (double)(ec + ev + ed);
        }
    }

    // warp reduce (double), then one shared-atomic per warp, one global per block
    #pragma unroll
    for (int o = 16; o > 0; o >>= 1)
        acc += __shfl_down_sync(0xffffffffu, acc, o);
    if (lane == 0 && acc != 0.0) atomicAdd(&sAcc, acc);
    __syncthreads();
    if (threadIdx.x == 0 && sAcc != 0.0) atomicAdd(&g_energy, sAcc);
}

// ---------------------------------------------------------------------------
// Kernel 3: write the scalar output (LONG_RANGE_SCALE = 1.0)
// ---------------------------------------------------------------------------
__global__ void final_kernel(float* __restrict__ out) {
    out[0] = (float)g_energy;
}

// ---------------------------------------------------------------------------
extern "C" void kernel_launch(void* const* d_in, const int* in_sizes, int n_in,
                              void* d_out, int out_size) {
    const float* h0   = (const float*)d_in[0];
    const float* h1   = (const float*)d_in[1];
    const float* pos  = (const float*)d_in[2];
    const int*   batch= (const int*)  d_in[3];
    const float* qW1  = (const float*)d_in[4];
    const float* qb1  = (const float*)d_in[5];
    const float* qW2  = (const float*)d_in[6];
    const float* qb2  = (const float*)d_in[7];
    const float* cW1  = (const float*)d_in[8];
    const float* cb1  = (const float*)d_in[9];
    const float* cW2  = (const float*)d_in[10];
    const float* cb2  = (const float*)d_in[11];
    const float* muW  = (const float*)d_in[12];

    init_kernel<<<1, 64>>>();
    atom_kernel<<<NATOM_BLOCKS, 128>>>(h0, h1, batch,
                                       qW1, qb1, qW2, qb2,
                                       cW1, cb1, cW2, cb2, muW);
    pair_kernel<<<NATOMS * 32 / 256, 256>>>(pos, batch);
    final_kernel<<<1, 1>>>((float*)d_out);
}